// round 1
// baseline (speedup 1.0000x reference)
#include <cuda_runtime.h>
#include <math.h>

#define Bsz 16
#define Nn 1024
#define Dd 512
#define Kk 8
#define NITERS 3
#define EPSV 1e-8f
#define LNEPS 1e-5f
#define LOG2PI 1.8378770664093453f
#define SPLITS 32
#define RPB (Nn / SPLITS)   // 32 rows per split block

// ------------------- scratch (device globals, no runtime alloc) -------------
__device__ float g_keys[Bsz * Nn * Dd];      // 32 MB
__device__ float g_values[Bsz * Nn * Dd];    // 32 MB
__device__ float g_mean[Bsz * Nn];
__device__ float g_rstd[Bsz * Nn];
__device__ float g_q[Bsz * Kk * Dd];
__device__ float g_sigma[Bsz * Kk * Dd];
__device__ float g_iv[Bsz * Kk * Dd];
__device__ float g_c[Bsz * Kk];
__device__ float g_mix[Bsz * Kk];
__device__ float g_attn[Bsz * Nn * Kk];      // 512 KB
__device__ float g_colsum[Bsz * Kk];
__device__ float g_mu[Bsz * Kk * Dd];
__device__ float g_part[Bsz * SPLITS * Kk * Dd];  // 8 MB

// ------------------- LayerNorm row stats ------------------------------------
__global__ void ln_stats_kernel(const float* __restrict__ emb) {
    int row = blockIdx.x;                       // 0 .. B*N-1
    const float4* p = (const float4*)(emb + (size_t)row * Dd);
    float4 v = p[threadIdx.x];                  // 128 threads * 4 = 512
    float s  = v.x + v.y + v.z + v.w;
    float ss = v.x * v.x + v.y * v.y + v.z * v.z + v.w * v.w;
#pragma unroll
    for (int o = 16; o > 0; o >>= 1) {
        s  += __shfl_down_sync(0xFFFFFFFFu, s, o);
        ss += __shfl_down_sync(0xFFFFFFFFu, ss, o);
    }
    __shared__ float sh[8];
    int w = threadIdx.x >> 5, l = threadIdx.x & 31;
    if (l == 0) { sh[w] = s; sh[4 + w] = ss; }
    __syncthreads();
    if (threadIdx.x == 0) {
        s  = sh[0] + sh[1] + sh[2] + sh[3];
        ss = sh[4] + sh[5] + sh[6] + sh[7];
        float m   = s / (float)Dd;
        float var = ss / (float)Dd - m * m;
        g_mean[row] = m;
        g_rstd[row] = rsqrtf(var + LNEPS);
    }
}

// ------------------- fused LN + GEMM for keys & values ----------------------
// C[16384, 1024] = ln(emb) @ [Wk | Wv] + [bk | bv]
#define BM 128
#define BN 128
#define BKK 8
__global__ __launch_bounds__(256, 2)
void gemm_kv_kernel(const float* __restrict__ emb,
                    const float* __restrict__ Wk, const float* __restrict__ bk,
                    const float* __restrict__ Wv, const float* __restrict__ bv,
                    const float* __restrict__ ln_g, const float* __restrict__ ln_b) {
    __shared__ float As[BKK][BM];
    __shared__ float Bs[BKK][BN];

    int bm = blockIdx.y * BM;          // row offset (0..16383)
    int bn = blockIdx.x * BN;          // col offset (0..1023)
    const float* W    = (bn < Dd) ? Wk : Wv;
    const float* bias = (bn < Dd) ? bk : bv;
    float* Cout       = (bn < Dd) ? g_keys : g_values;
    int coloff = bn & (Dd - 1);

    int tid = threadIdx.x;
    int arow = tid >> 1;               // 0..127
    int acol = (tid & 1) * 4;          // 0 or 4
    int brow = tid >> 5;               // 0..7
    int bcol = (tid & 31) * 4;         // 0..124

    float mean = g_mean[bm + arow];
    float rstd = g_rstd[bm + arow];

    float acc[8][8];
#pragma unroll
    for (int i = 0; i < 8; i++)
#pragma unroll
        for (int j = 0; j < 8; j++) acc[i][j] = 0.f;

    int tx = tid & 15, ty = tid >> 4;

    for (int k0 = 0; k0 < Dd; k0 += BKK) {
        float4 av = *(const float4*)&emb[(size_t)(bm + arow) * Dd + k0 + acol];
        float4 gg = *(const float4*)&ln_g[k0 + acol];
        float4 bb = *(const float4*)&ln_b[k0 + acol];
        As[acol + 0][arow] = (av.x - mean) * rstd * gg.x + bb.x;
        As[acol + 1][arow] = (av.y - mean) * rstd * gg.y + bb.y;
        As[acol + 2][arow] = (av.z - mean) * rstd * gg.z + bb.z;
        As[acol + 3][arow] = (av.w - mean) * rstd * gg.w + bb.w;

        float4 wv = *(const float4*)&W[(size_t)(k0 + brow) * Dd + coloff + bcol];
        *(float4*)&Bs[brow][bcol] = wv;
        __syncthreads();

#pragma unroll
        for (int kk = 0; kk < BKK; kk++) {
            float a[8], b[8];
            *(float4*)(a)     = *(const float4*)&As[kk][ty * 8];
            *(float4*)(a + 4) = *(const float4*)&As[kk][ty * 8 + 4];
            *(float4*)(b)     = *(const float4*)&Bs[kk][tx * 8];
            *(float4*)(b + 4) = *(const float4*)&Bs[kk][tx * 8 + 4];
#pragma unroll
            for (int i = 0; i < 8; i++)
#pragma unroll
                for (int j = 0; j < 8; j++) acc[i][j] += a[i] * b[j];
        }
        __syncthreads();
    }

#pragma unroll
    for (int i = 0; i < 8; i++) {
        int row = bm + ty * 8 + i;
#pragma unroll
        for (int j = 0; j < 8; j += 4) {
            int col = coloff + tx * 8 + j;
            float4 o;
            o.x = acc[i][j + 0] + bias[col + 0];
            o.y = acc[i][j + 1] + bias[col + 1];
            o.z = acc[i][j + 2] + bias[col + 2];
            o.w = acc[i][j + 3] + bias[col + 3];
            *(float4*)&Cout[(size_t)row * Dd + col] = o;
        }
    }
}

// ------------------- slots init + queries = slots @ Wq + bq -----------------
__global__ void qinit_kernel(const float* __restrict__ mu_s,
                             const float* __restrict__ logsig,
                             const float* __restrict__ noise,
                             const float* __restrict__ Wq,
                             const float* __restrict__ bq,
                             const float* __restrict__ mixc) {
    int bk = blockIdx.x;               // b*K + k
    int k = bk & (Kk - 1);
    __shared__ float srow[Dd];
    int t = threadIdx.x;               // 512
    float sg = expf(logsig[k * Dd + t]);
    g_sigma[bk * Dd + t] = sg;
    srow[t] = mu_s[k * Dd + t] + sg * noise[bk * Dd + t];
    if (t == 0) g_mix[bk] = mixc[k];
    __syncthreads();
    float acc = bq[t];
    for (int d = 0; d < Dd; d++) acc += srow[d] * Wq[d * Dd + t];
    g_q[bk * Dd + t] = acc;
}

// ------------------- per-(b,k) prep: inv-var and gll constant ---------------
__global__ void kprep_kernel() {
    int bk = blockIdx.x;
    int t = threadIdx.x;               // 256
    float ls = 0.f;
    for (int d = t; d < Dd; d += 256) {
        float s = g_sigma[bk * Dd + d];
        g_iv[bk * Dd + d] = 1.f / (s * s + EPSV);
        ls += logf(fabsf(s) + EPSV);
    }
#pragma unroll
    for (int o = 16; o > 0; o >>= 1) ls += __shfl_down_sync(0xFFFFFFFFu, ls, o);
    __shared__ float sh[8];
    int w = t >> 5, l = t & 31;
    if (l == 0) sh[w] = ls;
    __syncthreads();
    if (t == 0) {
        float tot = 0.f;
        for (int i = 0; i < 8; i++) tot += sh[i];
        g_c[bk] = -0.5f * (float)Dd * LOG2PI - 0.5f * tot;
    }
}

// ------------------- gll + row (K-axis) normalization -----------------------
#define GROWS 16
__global__ __launch_bounds__(256)
void gll_kernel() {
    int b = blockIdx.y;
    int chunk = blockIdx.x;
    __shared__ float q_sh[Kk * Dd];
    __shared__ float iv_sh[Kk * Dd];
    __shared__ float key_sh[Dd];
    __shared__ float att_sh[Kk];
    __shared__ float c_sh[Kk], mix_sh[Kk];
    int t = threadIdx.x;               // 256
    for (int i = t; i < Kk * Dd; i += 256) {
        q_sh[i]  = g_q[b * Kk * Dd + i];
        iv_sh[i] = g_iv[b * Kk * Dd + i];
    }
    if (t < Kk) { c_sh[t] = g_c[b * Kk + t]; mix_sh[t] = g_mix[b * Kk + t]; }
    __syncthreads();
    int w = t >> 5, lane = t & 31;
    const float* qp = q_sh + w * Dd;
    const float* ip = iv_sh + w * Dd;
    for (int r = 0; r < GROWS; r++) {
        int n = chunk * GROWS + r;
        const float* kr = g_keys + ((size_t)(b * Nn + n)) * Dd;
        for (int i = t; i < Dd; i += 256) key_sh[i] = kr[i];
        __syncthreads();
        float sum = 0.f;
#pragma unroll 4
        for (int d = lane; d < Dd; d += 32) {
            float df = key_sh[d] - qp[d];
            sum += df * df * ip[d];
        }
#pragma unroll
        for (int o = 16; o > 0; o >>= 1) sum += __shfl_down_sync(0xFFFFFFFFu, sum, o);
        if (lane == 0) att_sh[w] = mix_sh[w] * (c_sh[w] - 0.5f * sum);
        __syncthreads();
        if (t < Kk) {
            float rs = 0.f;
#pragma unroll
            for (int k2 = 0; k2 < Kk; k2++) rs += att_sh[k2];
            g_attn[((size_t)(b * Nn + n)) * Kk + t] = att_sh[t] / rs;
        }
        __syncthreads();
    }
}

// ------------------- column sums over n + mixing update ---------------------
__global__ void colsum_kernel() {
    int b = blockIdx.y, k = blockIdx.x;
    int t = threadIdx.x;               // 256
    float s = 0.f;
    for (int n = t; n < Nn; n += 256) s += g_attn[((size_t)(b * Nn + n)) * Kk + k];
#pragma unroll
    for (int o = 16; o > 0; o >>= 1) s += __shfl_down_sync(0xFFFFFFFFu, s, o);
    __shared__ float sh[8];
    int w = t >> 5, l = t & 31;
    if (l == 0) sh[w] = s;
    __syncthreads();
    if (t == 0) {
        float tot = 0.f;
        for (int i = 0; i < 8; i++) tot += sh[i];
        g_colsum[b * Kk + k] = tot;
        g_mix[b * Kk + k] = (tot / (tot + EPSV)) / (float)Nn;   // for next iter
    }
}

__global__ void norm_kernel() {
    int i = blockIdx.x * 256 + threadIdx.x;    // 131072 total
    int k = i & (Kk - 1);
    int b = i >> 13;                           // / (N*K)
    g_attn[i] = g_attn[i] / (g_colsum[b * Kk + k] + EPSV);
}

// ------------------- mu = attn^T @ values (split-n, deterministic) ----------
__global__ __launch_bounds__(512)
void mu_part_kernel() {
    int b = blockIdx.y, s = blockIdx.x;
    __shared__ float a_sh[RPB][Kk];
    int t = threadIdx.x;               // 512
    if (t < RPB * Kk)
        a_sh[t >> 3][t & 7] = g_attn[((size_t)(b * Nn + s * RPB)) * Kk + t];
    __syncthreads();
    float acc[Kk];
#pragma unroll
    for (int k = 0; k < Kk; k++) acc[k] = 0.f;
    for (int r = 0; r < RPB; r++) {
        float v = g_values[((size_t)(b * Nn + s * RPB + r)) * Dd + t];
#pragma unroll
        for (int k = 0; k < Kk; k++) acc[k] += a_sh[r][k] * v;
    }
#pragma unroll
    for (int k = 0; k < Kk; k++)
        g_part[(((size_t)b * SPLITS + s) * Kk + k) * Dd + t] = acc[k];
}

__global__ void mu_reduce_kernel() {
    int bk = blockIdx.x;
    int b = bk >> 3, k = bk & 7;
    int t = threadIdx.x;               // 512
    float m = 0.f;
    for (int s = 0; s < SPLITS; s++)
        m += g_part[(((size_t)b * SPLITS + s) * Kk + k) * Dd + t];
    g_mu[bk * Dd + t] = m;
}

// ------------------- sigma = sum_n attn * (v - mu)^2 ------------------------
__global__ __launch_bounds__(512)
void sig_part_kernel() {
    int b = blockIdx.y, s = blockIdx.x;
    __shared__ float a_sh[RPB][Kk];
    __shared__ float mu_sh[Kk * Dd];
    int t = threadIdx.x;               // 512
    if (t < RPB * Kk)
        a_sh[t >> 3][t & 7] = g_attn[((size_t)(b * Nn + s * RPB)) * Kk + t];
    for (int i = t; i < Kk * Dd; i += 512) mu_sh[i] = g_mu[b * Kk * Dd + i];
    __syncthreads();
    float acc[Kk];
#pragma unroll
    for (int k = 0; k < Kk; k++) acc[k] = 0.f;
    for (int r = 0; r < RPB; r++) {
        float v = g_values[((size_t)(b * Nn + s * RPB + r)) * Dd + t];
#pragma unroll
        for (int k = 0; k < Kk; k++) {
            float df = v - mu_sh[k * Dd + t];
            acc[k] += a_sh[r][k] * df * df;
        }
    }
#pragma unroll
    for (int k = 0; k < Kk; k++)
        g_part[(((size_t)b * SPLITS + s) * Kk + k) * Dd + t] = acc[k];
}

__global__ void sig_reduce_kernel() {
    int bk = blockIdx.x;
    int b = bk >> 3, k = bk & 7;
    int t = threadIdx.x;               // 512
    float m = 0.f;
    for (int s = 0; s < SPLITS; s++)
        m += g_part[(((size_t)b * SPLITS + s) * Kk + k) * Dd + t];
    g_sigma[bk * Dd + t] = m;
}

// ------------------- outputs ------------------------------------------------
__global__ void out_slots_kernel(const float* __restrict__ noise_final,
                                 float* __restrict__ out) {
    int bk = blockIdx.x;
    int t = threadIdx.x;               // 512
    int i = bk * Dd + t;
    float sg = fmaxf(fabsf(g_sigma[i]), EPSV);
    out[i] = g_mu[i] + sg * noise_final[i];
}

__global__ void out_attn_kernel(float* __restrict__ out) {
    int i = blockIdx.x * 256 + threadIdx.x;    // 131072
    int n = i & (Nn - 1);
    int k = (i >> 10) & (Kk - 1);
    int b = i >> 13;
    out[Bsz * Kk * Dd + i] = g_attn[((size_t)(b * Nn + n)) * Kk + k];
}

// ------------------- launch -------------------------------------------------
extern "C" void kernel_launch(void* const* d_in, const int* in_sizes, int n_in,
                              void* d_out, int out_size) {
    const float* embeddings  = (const float*)d_in[0];
    const float* noise_init  = (const float*)d_in[1];
    const float* noise_final = (const float*)d_in[2];
    const float* slots_mu    = (const float*)d_in[3];
    const float* slots_ls    = (const float*)d_in[4];
    const float* mixc        = (const float*)d_in[5];
    const float* Wk          = (const float*)d_in[6];
    const float* bk          = (const float*)d_in[7];
    const float* Wq          = (const float*)d_in[8];
    const float* bq          = (const float*)d_in[9];
    const float* Wv          = (const float*)d_in[10];
    const float* bv          = (const float*)d_in[11];
    const float* ln_g        = (const float*)d_in[12];
    const float* ln_b        = (const float*)d_in[13];
    float* out = (float*)d_out;

    ln_stats_kernel<<<Bsz * Nn, 128>>>(embeddings);
    gemm_kv_kernel<<<dim3(1024 / BN, (Bsz * Nn) / BM), 256>>>(
        embeddings, Wk, bk, Wv, bv, ln_g, ln_b);
    qinit_kernel<<<Bsz * Kk, Dd>>>(slots_mu, slots_ls, noise_init, Wq, bq, mixc);

    for (int it = 0; it < NITERS; it++) {
        kprep_kernel<<<Bsz * Kk, 256>>>();
        gll_kernel<<<dim3(Nn / GROWS, Bsz), 256>>>();
        colsum_kernel<<<dim3(Kk, Bsz), 256>>>();
        norm_kernel<<<(Bsz * Nn * Kk) / 256, 256>>>();
        mu_part_kernel<<<dim3(SPLITS, Bsz), Dd>>>();
        mu_reduce_kernel<<<Bsz * Kk, Dd>>>();
        sig_part_kernel<<<dim3(SPLITS, Bsz), Dd>>>();
        sig_reduce_kernel<<<Bsz * Kk, Dd>>>();
    }

    out_slots_kernel<<<Bsz * Kk, Dd>>>(noise_final, out);
    out_attn_kernel<<<(Bsz * Nn * Kk) / 256, 256>>>(out);
}

// round 2
// speedup vs baseline: 1.4793x; 1.4793x over previous
#include <cuda_runtime.h>
#include <math.h>

#define Bsz 16
#define Nn 1024
#define Dd 512
#define Kk 8
#define NITERS 3
#define EPSV 1e-8f
#define LNEPS 1e-5f
#define LOG2PI 1.8378770664093453f
#define SPLITS 32
#define RPB (Nn / SPLITS)   // 32 rows per split block

// ------------------- scratch (device globals, no runtime alloc) -------------
__device__ float g_keys[Bsz * Nn * Dd];      // 32 MB
__device__ float g_values[Bsz * Nn * Dd];    // 32 MB
__device__ float g_mean[Bsz * Nn];
__device__ float g_rstd[Bsz * Nn];
__device__ float g_q[Bsz * Kk * Dd];
__device__ float g_sigma[Bsz * Kk * Dd];
__device__ float g_iv[Bsz * Kk * Dd];
__device__ float g_c[Bsz * Kk];
__device__ float g_mix[Bsz * Kk];
__device__ float g_attn[Bsz * Nn * Kk];      // 512 KB
__device__ float g_colsum[Bsz * Kk];
__device__ float g_snorm[Bsz * Kk];
__device__ float g_mu[Bsz * Kk * Dd];
__device__ float g_part[Bsz * SPLITS * Kk * Dd];   // 8 MB  (sum a*v)
__device__ float g_part2[Bsz * SPLITS * Kk * Dd];  // 8 MB  (sum a*v*v)

__device__ __forceinline__ unsigned f2tf32(float x) {
    unsigned y;
    asm("cvt.rna.tf32.f32 %0, %1;" : "=r"(y) : "f"(x));
    return y;
}

// ------------------- LayerNorm row stats ------------------------------------
__global__ void ln_stats_kernel(const float* __restrict__ emb) {
    int row = blockIdx.x;                       // 0 .. B*N-1
    const float4* p = (const float4*)(emb + (size_t)row * Dd);
    float4 v = p[threadIdx.x];                  // 128 threads * 4 = 512
    float s  = v.x + v.y + v.z + v.w;
    float ss = v.x * v.x + v.y * v.y + v.z * v.z + v.w * v.w;
#pragma unroll
    for (int o = 16; o > 0; o >>= 1) {
        s  += __shfl_down_sync(0xFFFFFFFFu, s, o);
        ss += __shfl_down_sync(0xFFFFFFFFu, ss, o);
    }
    __shared__ float sh[8];
    int w = threadIdx.x >> 5, l = threadIdx.x & 31;
    if (l == 0) { sh[w] = s; sh[4 + w] = ss; }
    __syncthreads();
    if (threadIdx.x == 0) {
        s  = sh[0] + sh[1] + sh[2] + sh[3];
        ss = sh[4] + sh[5] + sh[6] + sh[7];
        float m   = s / (float)Dd;
        float var = ss / (float)Dd - m * m;
        g_mean[row] = m;
        g_rstd[row] = rsqrtf(var + LNEPS);
    }
}

// ------------------- fused LN + tf32 tensor-core GEMM for keys & values -----
// C[16384, 1024] = ln(emb) @ [Wk | Wv] + [bk | bv], tf32 mma.sync.m16n8k8
#define GBM 128
#define GBN 128
#define GBK 16
__global__ __launch_bounds__(256)
void gemm_kv_tf32(const float* __restrict__ emb,
                  const float* __restrict__ Wk, const float* __restrict__ bk,
                  const float* __restrict__ Wv, const float* __restrict__ bv,
                  const float* __restrict__ ln_g, const float* __restrict__ ln_b) {
    __shared__ unsigned As[2][GBK][GBM + 4];   // k-major A (tf32 bits)
    __shared__ unsigned Bs[2][GBK][GBN + 4];   // k-major B (tf32 bits)

    int bm = blockIdx.y * GBM;
    int bn = blockIdx.x * GBN;
    const float* W    = (bn < Dd) ? Wk : Wv;
    const float* bias = (bn < Dd) ? bk : bv;
    float* Cout       = (bn < Dd) ? g_keys : g_values;
    int coloff = bn & (Dd - 1);

    int tid  = threadIdx.x;
    int arow = tid >> 1;               // 0..127
    int aq   = tid & 1;                // k half: 0..7 / 8..15
    float mean = g_mean[bm + arow];
    float rstd = g_rstd[bm + arow];

    int lane = tid & 31, wrp = tid >> 5;
    int warpM = (wrp & 1) * 64, warpN = (wrp >> 1) * 32;
    int g  = lane >> 2, ti = lane & 3;

    float acc[4][4][4];
#pragma unroll
    for (int mf = 0; mf < 4; mf++)
#pragma unroll
        for (int nf = 0; nf < 4; nf++)
#pragma unroll
            for (int c = 0; c < 4; c++) acc[mf][nf][c] = 0.f;

    // prefetch registers
    float4 pa[2], pw[2];
    int k0s = 0;

    // ---- prologue: load tile 0 ----
#pragma unroll
    for (int i = 0; i < 2; i++) {
        int k = aq * 8 + i * 4;
        pa[i] = *(const float4*)&emb[(size_t)(bm + arow) * Dd + 0 + k];
        int idx = i * 256 + tid;
        int brow = idx >> 5, bcol = (idx & 31) * 4;
        pw[i] = *(const float4*)&W[(size_t)(0 + brow) * Dd + coloff + bcol];
    }
    // ---- store tile 0 ----
#pragma unroll
    for (int i = 0; i < 2; i++) {
        int k = aq * 8 + i * 4;
        float4 gg = *(const float4*)&ln_g[k0s + k];
        float4 bb = *(const float4*)&ln_b[k0s + k];
        As[0][k + 0][arow] = f2tf32((pa[i].x - mean) * rstd * gg.x + bb.x);
        As[0][k + 1][arow] = f2tf32((pa[i].y - mean) * rstd * gg.y + bb.y);
        As[0][k + 2][arow] = f2tf32((pa[i].z - mean) * rstd * gg.z + bb.z);
        As[0][k + 3][arow] = f2tf32((pa[i].w - mean) * rstd * gg.w + bb.w);
        int idx = i * 256 + tid;
        int brow = idx >> 5, bcol = (idx & 31) * 4;
        Bs[0][brow][bcol + 0] = f2tf32(pw[i].x);
        Bs[0][brow][bcol + 1] = f2tf32(pw[i].y);
        Bs[0][brow][bcol + 2] = f2tf32(pw[i].z);
        Bs[0][brow][bcol + 3] = f2tf32(pw[i].w);
    }
    __syncthreads();

    int p = 0;
    const int NSTEP = Dd / GBK;        // 32
    for (int step = 0; step < NSTEP; step++) {
        int k0n = (step + 1) * GBK;
        if (step + 1 < NSTEP) {
            // prefetch next tile into registers
#pragma unroll
            for (int i = 0; i < 2; i++) {
                int k = aq * 8 + i * 4;
                pa[i] = *(const float4*)&emb[(size_t)(bm + arow) * Dd + k0n + k];
                int idx = i * 256 + tid;
                int brow = idx >> 5, bcol = (idx & 31) * 4;
                pw[i] = *(const float4*)&W[(size_t)(k0n + brow) * Dd + coloff + bcol];
            }
        }
        // ---- compute on buffer p ----
#pragma unroll
        for (int kk = 0; kk < GBK / 8; kk++) {
            int kb = kk * 8;
            unsigned af[4][4], bf[4][2];
#pragma unroll
            for (int mf = 0; mf < 4; mf++) {
                int m = warpM + mf * 16 + g;
                af[mf][0] = As[p][kb + ti][m];
                af[mf][1] = As[p][kb + ti][m + 8];
                af[mf][2] = As[p][kb + ti + 4][m];
                af[mf][3] = As[p][kb + ti + 4][m + 8];
            }
#pragma unroll
            for (int nf = 0; nf < 4; nf++) {
                int n = warpN + nf * 8 + g;
                bf[nf][0] = Bs[p][kb + ti][n];
                bf[nf][1] = Bs[p][kb + ti + 4][n];
            }
#pragma unroll
            for (int mf = 0; mf < 4; mf++)
#pragma unroll
                for (int nf = 0; nf < 4; nf++) {
                    asm volatile(
                        "mma.sync.aligned.m16n8k8.row.col.f32.tf32.tf32.f32 "
                        "{%0,%1,%2,%3}, {%4,%5,%6,%7}, {%8,%9}, {%0,%1,%2,%3};"
                        : "+f"(acc[mf][nf][0]), "+f"(acc[mf][nf][1]),
                          "+f"(acc[mf][nf][2]), "+f"(acc[mf][nf][3])
                        : "r"(af[mf][0]), "r"(af[mf][1]),
                          "r"(af[mf][2]), "r"(af[mf][3]),
                          "r"(bf[nf][0]), "r"(bf[nf][1]));
                }
        }
        if (step + 1 < NSTEP) {
            int np = p ^ 1;
            k0s = k0n;
#pragma unroll
            for (int i = 0; i < 2; i++) {
                int k = aq * 8 + i * 4;
                float4 gg = *(const float4*)&ln_g[k0s + k];
                float4 bb = *(const float4*)&ln_b[k0s + k];
                As[np][k + 0][arow] = f2tf32((pa[i].x - mean) * rstd * gg.x + bb.x);
                As[np][k + 1][arow] = f2tf32((pa[i].y - mean) * rstd * gg.y + bb.y);
                As[np][k + 2][arow] = f2tf32((pa[i].z - mean) * rstd * gg.z + bb.z);
                As[np][k + 3][arow] = f2tf32((pa[i].w - mean) * rstd * gg.w + bb.w);
                int idx = i * 256 + tid;
                int brow = idx >> 5, bcol = (idx & 31) * 4;
                Bs[np][brow][bcol + 0] = f2tf32(pw[i].x);
                Bs[np][brow][bcol + 1] = f2tf32(pw[i].y);
                Bs[np][brow][bcol + 2] = f2tf32(pw[i].z);
                Bs[np][brow][bcol + 3] = f2tf32(pw[i].w);
            }
            __syncthreads();
            p = np;
        }
    }

    // ---- epilogue ----
#pragma unroll
    for (int mf = 0; mf < 4; mf++) {
        int row = bm + warpM + mf * 16 + g;
#pragma unroll
        for (int nf = 0; nf < 4; nf++) {
            int col = coloff + warpN + nf * 8 + 2 * ti;
            float2 v0, v1;
            v0.x = acc[mf][nf][0] + bias[col];
            v0.y = acc[mf][nf][1] + bias[col + 1];
            v1.x = acc[mf][nf][2] + bias[col];
            v1.y = acc[mf][nf][3] + bias[col + 1];
            *(float2*)&Cout[(size_t)row * Dd + col] = v0;
            *(float2*)&Cout[(size_t)(row + 8) * Dd + col] = v1;
        }
    }
}

// ------------------- slots init + queries = slots @ Wq + bq -----------------
// one block per batch: Wq read once per block (16 MB total L2 traffic)
__global__ __launch_bounds__(512)
void qinit_kernel(const float* __restrict__ mu_s,
                  const float* __restrict__ logsig,
                  const float* __restrict__ noise,
                  const float* __restrict__ Wq,
                  const float* __restrict__ bq,
                  const float* __restrict__ mixc) {
    int b = blockIdx.x;
    int t = threadIdx.x;               // 512
    __shared__ float s_sh[Kk][Dd];     // 16 KB
#pragma unroll
    for (int k = 0; k < Kk; k++) {
        float sg = expf(logsig[k * Dd + t]);
        g_sigma[(b * Kk + k) * Dd + t] = sg;
        s_sh[k][t] = mu_s[k * Dd + t] + sg * noise[(b * Kk + k) * Dd + t];
    }
    if (t < Kk) g_mix[b * Kk + t] = mixc[t];
    __syncthreads();
    float acc[Kk];
    float bqv = bq[t];
#pragma unroll
    for (int k = 0; k < Kk; k++) acc[k] = bqv;
    for (int d = 0; d < Dd; d += 4) {
        float4 w0;
        w0.x = Wq[(d + 0) * Dd + t];
        w0.y = Wq[(d + 1) * Dd + t];
        w0.z = Wq[(d + 2) * Dd + t];
        w0.w = Wq[(d + 3) * Dd + t];
#pragma unroll
        for (int k = 0; k < Kk; k++) {
            float4 s4 = *(const float4*)&s_sh[k][d];
            acc[k] += s4.x * w0.x + s4.y * w0.y + s4.z * w0.z + s4.w * w0.w;
        }
    }
#pragma unroll
    for (int k = 0; k < Kk; k++) g_q[(b * Kk + k) * Dd + t] = acc[k];
}

// ------------------- per-(b,k) prep: inv-var and gll constant ---------------
__global__ void kprep_kernel() {
    int bk = blockIdx.x;
    int t = threadIdx.x;               // 256
    float ls = 0.f;
    for (int d = t; d < Dd; d += 256) {
        float s = g_sigma[bk * Dd + d];
        g_iv[bk * Dd + d] = 1.f / (s * s + EPSV);
        ls += logf(fabsf(s) + EPSV);
    }
#pragma unroll
    for (int o = 16; o > 0; o >>= 1) ls += __shfl_down_sync(0xFFFFFFFFu, ls, o);
    __shared__ float sh[8];
    int w = t >> 5, l = t & 31;
    if (l == 0) sh[w] = ls;
    __syncthreads();
    if (t == 0) {
        float tot = 0.f;
        for (int i = 0; i < 8; i++) tot += sh[i];
        g_c[bk] = -0.5f * (float)Dd * LOG2PI - 0.5f * tot;
    }
}

// ------------------- gll + row (K-axis) normalization -----------------------
#define GROWS 16
__global__ __launch_bounds__(256)
void gll_kernel() {
    int b = blockIdx.y;
    int chunk = blockIdx.x;
    __shared__ float q_sh[Kk * Dd];
    __shared__ float iv_sh[Kk * Dd];
    __shared__ float key_sh[Dd];
    __shared__ float att_sh[Kk];
    __shared__ float c_sh[Kk], mix_sh[Kk];
    int t = threadIdx.x;               // 256
    for (int i = t; i < Kk * Dd; i += 256) {
        q_sh[i]  = g_q[b * Kk * Dd + i];
        iv_sh[i] = g_iv[b * Kk * Dd + i];
    }
    if (t < Kk) { c_sh[t] = g_c[b * Kk + t]; mix_sh[t] = g_mix[b * Kk + t]; }
    __syncthreads();
    int w = t >> 5, lane = t & 31;
    const float* qp = q_sh + w * Dd;
    const float* ip = iv_sh + w * Dd;
    for (int r = 0; r < GROWS; r++) {
        int n = chunk * GROWS + r;
        const float* kr = g_keys + ((size_t)(b * Nn + n)) * Dd;
        for (int i = t; i < Dd; i += 256) key_sh[i] = kr[i];
        __syncthreads();
        float sum = 0.f;
#pragma unroll 4
        for (int d = lane; d < Dd; d += 32) {
            float df = key_sh[d] - qp[d];
            sum += df * df * ip[d];
        }
#pragma unroll
        for (int o = 16; o > 0; o >>= 1) sum += __shfl_down_sync(0xFFFFFFFFu, sum, o);
        if (lane == 0) att_sh[w] = mix_sh[w] * (c_sh[w] - 0.5f * sum);
        __syncthreads();
        if (t < Kk) {
            float rs = 0.f;
#pragma unroll
            for (int k2 = 0; k2 < Kk; k2++) rs += att_sh[k2];
            g_attn[((size_t)(b * Nn + n)) * Kk + t] = att_sh[t] / rs;
        }
        __syncthreads();
    }
}

// ------------------- column sums over n + mixing update ---------------------
__global__ void colsum_kernel() {
    int b = blockIdx.y, k = blockIdx.x;
    int t = threadIdx.x;               // 256
    float s = 0.f;
    for (int n = t; n < Nn; n += 256) s += g_attn[((size_t)(b * Nn + n)) * Kk + k];
#pragma unroll
    for (int o = 16; o > 0; o >>= 1) s += __shfl_down_sync(0xFFFFFFFFu, s, o);
    __shared__ float sh[8];
    int w = t >> 5, l = t & 31;
    if (l == 0) sh[w] = s;
    __syncthreads();
    if (t == 0) {
        float tot = 0.f;
        for (int i = 0; i < 8; i++) tot += sh[i];
        g_colsum[b * Kk + k] = tot;
        g_snorm[b * Kk + k] = tot / (tot + EPSV);           // sum of normalized attn col
        g_mix[b * Kk + k] = (tot / (tot + EPSV)) / (float)Nn;   // next-iter mixing
    }
}

__global__ void norm_kernel() {
    int i = blockIdx.x * 256 + threadIdx.x;    // 131072 total
    int k = i & (Kk - 1);
    int b = i >> 13;                           // / (N*K)
    g_attn[i] = g_attn[i] / (g_colsum[b * Kk + k] + EPSV);
}

// ------------ fused mu & sigma partials: sum a*v and sum a*v^2 --------------
__global__ __launch_bounds__(512)
void musig_part_kernel() {
    int b = blockIdx.y, s = blockIdx.x;
    __shared__ float a_sh[RPB][Kk];
    int t = threadIdx.x;               // 512
    if (t < RPB * Kk)
        a_sh[t >> 3][t & 7] = g_attn[((size_t)(b * Nn + s * RPB)) * Kk + t];
    __syncthreads();
    float acc1[Kk], acc2[Kk];
#pragma unroll
    for (int k = 0; k < Kk; k++) { acc1[k] = 0.f; acc2[k] = 0.f; }
    for (int r = 0; r < RPB; r++) {
        float v = g_values[((size_t)(b * Nn + s * RPB + r)) * Dd + t];
        float v2 = v * v;
#pragma unroll
        for (int k = 0; k < Kk; k++) {
            float a = a_sh[r][k];
            acc1[k] += a * v;
            acc2[k] += a * v2;
        }
    }
#pragma unroll
    for (int k = 0; k < Kk; k++) {
        size_t idx = (((size_t)b * SPLITS + s) * Kk + k) * Dd + t;
        g_part[idx]  = acc1[k];
        g_part2[idx] = acc2[k];
    }
}

// mu = sum parts; sigma = E[a v^2] - (2 - s) mu^2   (exact since sum_n a = s)
__global__ void musig_reduce_kernel() {
    int bk = blockIdx.x;
    int b = bk >> 3, k = bk & 7;
    int t = threadIdx.x;               // 512
    float m = 0.f, q2 = 0.f;
    for (int s = 0; s < SPLITS; s++) {
        size_t idx = (((size_t)b * SPLITS + s) * Kk + k) * Dd + t;
        m  += g_part[idx];
        q2 += g_part2[idx];
    }
    float sfac = g_snorm[bk];
    g_mu[bk * Dd + t] = m;
    g_sigma[bk * Dd + t] = q2 - (2.f - sfac) * m * m;
}

// ------------------- outputs ------------------------------------------------
__global__ void out_slots_kernel(const float* __restrict__ noise_final,
                                 float* __restrict__ out) {
    int bk = blockIdx.x;
    int t = threadIdx.x;               // 512
    int i = bk * Dd + t;
    float sg = fmaxf(fabsf(g_sigma[i]), EPSV);
    out[i] = g_mu[i] + sg * noise_final[i];
}

__global__ void out_attn_kernel(float* __restrict__ out) {
    int i = blockIdx.x * 256 + threadIdx.x;    // 131072
    int n = i & (Nn - 1);
    int k = (i >> 10) & (Kk - 1);
    int b = i >> 13;
    out[Bsz * Kk * Dd + i] = g_attn[((size_t)(b * Nn + n)) * Kk + k];
}

// ------------------- launch -------------------------------------------------
extern "C" void kernel_launch(void* const* d_in, const int* in_sizes, int n_in,
                              void* d_out, int out_size) {
    const float* embeddings  = (const float*)d_in[0];
    const float* noise_init  = (const float*)d_in[1];
    const float* noise_final = (const float*)d_in[2];
    const float* slots_mu    = (const float*)d_in[3];
    const float* slots_ls    = (const float*)d_in[4];
    const float* mixc        = (const float*)d_in[5];
    const float* Wk          = (const float*)d_in[6];
    const float* bk          = (const float*)d_in[7];
    const float* Wq          = (const float*)d_in[8];
    const float* bq          = (const float*)d_in[9];
    const float* Wv          = (const float*)d_in[10];
    const float* bv          = (const float*)d_in[11];
    const float* ln_g        = (const float*)d_in[12];
    const float* ln_b        = (const float*)d_in[13];
    float* out = (float*)d_out;

    ln_stats_kernel<<<Bsz * Nn, 128>>>(embeddings);
    gemm_kv_tf32<<<dim3(1024 / GBN, (Bsz * Nn) / GBM), 256>>>(
        embeddings, Wk, bk, Wv, bv, ln_g, ln_b);
    qinit_kernel<<<Bsz, 512>>>(slots_mu, slots_ls, noise_init, Wq, bq, mixc);

    for (int it = 0; it < NITERS; it++) {
        kprep_kernel<<<Bsz * Kk, 256>>>();
        gll_kernel<<<dim3(Nn / GROWS, Bsz), 256>>>();
        colsum_kernel<<<dim3(Kk, Bsz), 256>>>();
        norm_kernel<<<(Bsz * Nn * Kk) / 256, 256>>>();
        musig_part_kernel<<<dim3(SPLITS, Bsz), 512>>>();
        musig_reduce_kernel<<<Bsz * Kk, 512>>>();
    }

    out_slots_kernel<<<Bsz * Kk, Dd>>>(noise_final, out);
    out_attn_kernel<<<(Bsz * Nn * Kk) / 256, 256>>>(out);
}